// round 11
// baseline (speedup 1.0000x reference)
#include <cuda_runtime.h>
#include <cuda_bf16.h>
#include <math.h>
#include <stdint.h>

#define NGRAPH 64
#define LNODES 2048
#define DDIM   128
#define GSPLIT 16                     // 128-row slices per graph for Gram

// ---------------- global scratch ----------------
__device__ float g_gram_part[NGRAPH * GSPLIT * DDIM * DDIM];   // 64 MB fp32 partials
__device__ __nv_bfloat16 g_gram_hi[NGRAPH * DDIM * DDIM];      // row-major n x k
__device__ __nv_bfloat16 g_gram_lo[NGRAPH * DDIM * DDIM];
__device__ __nv_bfloat16 g_w2_hi[DDIM * DDIM];                 // [p][d] = hi(w[p][d]^2)
__device__ __nv_bfloat16 g_w2_lo[DDIM * DDIM];

// ---------------- helpers ----------------
__device__ __forceinline__ void split2(float x, float y, uint32_t& hi, uint32_t& lo) {
    __nv_bfloat16 hx = __float2bfloat16_rn(x), hy = __float2bfloat16_rn(y);
    float rx = x - __bfloat162float(hx);
    float ry = y - __bfloat162float(hy);
    __nv_bfloat16 lx = __float2bfloat16_rn(rx), ly = __float2bfloat16_rn(ry);
    __nv_bfloat162 h = __halves2bfloat162(hx, hy);
    __nv_bfloat162 l = __halves2bfloat162(lx, ly);
    hi = *reinterpret_cast<uint32_t*>(&h);
    lo = *reinterpret_cast<uint32_t*>(&l);
}

// D += A * B, fp32 accum, m16n8k16 bf16.
__device__ __forceinline__ void mma_bf16(float d[4], const uint32_t a[4],
                                         uint32_t b0, uint32_t b1) {
    asm volatile(
        "mma.sync.aligned.m16n8k16.row.col.f32.bf16.bf16.f32 "
        "{%0,%1,%2,%3}, {%4,%5,%6,%7}, {%8,%9}, {%0,%1,%2,%3};"
        : "+f"(d[0]), "+f"(d[1]), "+f"(d[2]), "+f"(d[3])
        : "r"(a[0]), "r"(a[1]), "r"(a[2]), "r"(a[3]), "r"(b0), "r"(b1));
}

// ---------------------------------------------------------------------------
// k_w2: split w^2 -> bf16 hi/lo row-major [p][d]
// ---------------------------------------------------------------------------
__global__ void k_w2(const float* __restrict__ w) {
    int idx = blockIdx.x * 256 + threadIdx.x;
    float v = w[idx];
    float s = v * v;
    __nv_bfloat16 hi = __float2bfloat16_rn(s);
    __nv_bfloat16 lo = __float2bfloat16_rn(s - __bfloat162float(hi));
    g_w2_hi[idx] = hi;
    g_w2_lo[idx] = lo;
}

// ---------------------------------------------------------------------------
// k_gram_t: tensorized Gram partial. Block = one 128-row slice of one graph.
// Stage A: coalesced fp32 load; Stage B: transpose-split to bf16 hi/lo
// (odd uint32 stride 65 -> conflict-free); Stage C: 3-chain MMA (A==B buffer).
// SMEM: Xs f32[128][132] @0 (67584), Th bf16[128][130] @67584 (33280),
//       Tl @100864 (33280) -> 134144 B
// ---------------------------------------------------------------------------
#define XS_STR 132
#define GT_STR 130
#define SMEM_GRAM 134144

__global__ void __launch_bounds__(256) k_gram_t(const float* __restrict__ feats) {
    extern __shared__ char smg[];
    float* Xs = (float*)smg;
    __nv_bfloat16* Th = (__nv_bfloat16*)(smg + 67584);
    __nv_bfloat16* Tl = (__nv_bfloat16*)(smg + 100864);

    int b = blockIdx.x;                 // 0..1023
    int gj = b >> 4, s = b & 15;
    int tid = threadIdx.x, wid = tid >> 5, lid = tid & 31;
    int grp = lid >> 2, qid = lid & 3;
    int ra = wid * 16 + grp;

    // Stage A: coalesced load X[128][128]
    const float4* X4 = (const float4*)(feats + ((size_t)gj * LNODES + (size_t)s * 128) * DDIM);
#pragma unroll
    for (int t = 0; t < 16; t++) {
        int i = tid + t * 256;
        int r = i >> 5, c4 = i & 31;
        *(float4*)&Xs[r * XS_STR + c4 * 4] = X4[i];
    }
    __syncthreads();

    // Stage B: transpose + split. warp = 32 consecutive d, same l-pair.
#pragma unroll 4
    for (int it = 0; it < 32; it++) {
        int t = tid + it * 256;
        int d = t & 127, lp = t >> 7;   // lp 0..63
        float x0 = Xs[(2 * lp) * XS_STR + d];
        float x1 = Xs[(2 * lp + 1) * XS_STR + d];
        uint32_t h, l;
        split2(x0, x1, h, l);
        *(uint32_t*)&Th[d * GT_STR + 2 * lp] = h;
        *(uint32_t*)&Tl[d * GT_STR + 2 * lp] = l;
    }
    __syncthreads();

    // Stage C: Gram[128x128] partial via 3-chain bf16 MMA, A==B==T
    float acc[16][4];
#pragma unroll
    for (int n = 0; n < 16; n++)
#pragma unroll
        for (int j = 0; j < 4; j++) acc[n][j] = 0.f;

#pragma unroll 1
    for (int kt = 0; kt < 8; kt++) {
        int k0 = kt * 16 + qid * 2;
        uint32_t ah[4], al[4];
        ah[0] = *(const uint32_t*)&Th[ra * GT_STR + k0];
        ah[1] = *(const uint32_t*)&Th[(ra + 8) * GT_STR + k0];
        ah[2] = *(const uint32_t*)&Th[ra * GT_STR + k0 + 8];
        ah[3] = *(const uint32_t*)&Th[(ra + 8) * GT_STR + k0 + 8];
        al[0] = *(const uint32_t*)&Tl[ra * GT_STR + k0];
        al[1] = *(const uint32_t*)&Tl[(ra + 8) * GT_STR + k0];
        al[2] = *(const uint32_t*)&Tl[ra * GT_STR + k0 + 8];
        al[3] = *(const uint32_t*)&Tl[(ra + 8) * GT_STR + k0 + 8];
#pragma unroll
        for (int nt = 0; nt < 16; nt += 2) {
            int bnA = nt * 8 + grp, bnB = (nt + 1) * 8 + grp;
            uint32_t bh0a = *(const uint32_t*)&Th[bnA * GT_STR + k0];
            uint32_t bh1a = *(const uint32_t*)&Th[bnA * GT_STR + k0 + 8];
            uint32_t bl0a = *(const uint32_t*)&Tl[bnA * GT_STR + k0];
            uint32_t bl1a = *(const uint32_t*)&Tl[bnA * GT_STR + k0 + 8];
            uint32_t bh0b = *(const uint32_t*)&Th[bnB * GT_STR + k0];
            uint32_t bh1b = *(const uint32_t*)&Th[bnB * GT_STR + k0 + 8];
            uint32_t bl0b = *(const uint32_t*)&Tl[bnB * GT_STR + k0];
            uint32_t bl1b = *(const uint32_t*)&Tl[bnB * GT_STR + k0 + 8];
            mma_bf16(acc[nt],     ah, bh0a, bh1a);
            mma_bf16(acc[nt + 1], ah, bh0b, bh1b);
            mma_bf16(acc[nt],     ah, bl0a, bl1a);
            mma_bf16(acc[nt + 1], ah, bl0b, bl1b);
            mma_bf16(acc[nt],     al, bh0a, bh1a);
            mma_bf16(acc[nt + 1], al, bh0b, bh1b);
        }
    }
    // write partial
    float* outp = g_gram_part + (size_t)b * DDIM * DDIM;
#pragma unroll
    for (int nt = 0; nt < 16; nt++) {
        int c = nt * 8 + qid * 2;
        *(float2*)&outp[ra * DDIM + c]       = make_float2(acc[nt][0], acc[nt][1]);
        *(float2*)&outp[(ra + 8) * DDIM + c] = make_float2(acc[nt][2], acc[nt][3]);
    }
}

// ---------------------------------------------------------------------------
// k_gsplit: sum 16 partials -> bf16 hi/lo row-major
// ---------------------------------------------------------------------------
__global__ void k_gsplit() {
    int g = blockIdx.x;
    const float* gp = g_gram_part + (size_t)g * GSPLIT * DDIM * DDIM;
    __nv_bfloat16* bh = g_gram_hi + (size_t)g * DDIM * DDIM;
    __nv_bfloat16* bl = g_gram_lo + (size_t)g * DDIM * DDIM;
    for (int e = threadIdx.x; e < DDIM * DDIM; e += 256) {
        float s = 0.f;
#pragma unroll
        for (int p = 0; p < GSPLIT; p++) s += gp[(size_t)p * DDIM * DDIM + e];
        __nv_bfloat16 hi = __float2bfloat16_rn(s);
        __nv_bfloat16 lo = __float2bfloat16_rn(s - __bfloat162float(hi));
        bh[e] = hi;
        bl[e] = lo;
    }
}

// ---------------------------------------------------------------------------
// k_main: mma.sync bf16-split, dependency-interleaved issue.
// SMEM: V1 f32[128][132] @0, V2 f32[128][132] @67584,
//       Bh bf16[128][136] @135168, Bl bf16[128][136] @169984  (204800 B)
// ---------------------------------------------------------------------------
#define V1_STR 132
#define B_STR  136
#define SMEM_MAIN 204800

__global__ void __launch_bounds__(256) k_main(const float* __restrict__ feats,
                                              float* __restrict__ out) {
    extern __shared__ char sm[];
    float* V1 = (float*)sm;
    float* V2 = (float*)(sm + 67584);
    __nv_bfloat16* Bh = (__nv_bfloat16*)(sm + 135168);
    __nv_bfloat16* Bl = (__nv_bfloat16*)(sm + 169984);

    int tid = threadIdx.x, wid = tid >> 5, lid = tid & 31;
    int grp = lid >> 2, qid = lid & 3;
    int b = blockIdx.x, gj = b >> 4, tile = b & 15;
    int row0 = gj * LNODES + tile * 128;
    int ra = wid * 16 + grp;

    // ---- load V1 tile ----
    const float4* F4 = (const float4*)(feats + (size_t)row0 * DDIM);
#pragma unroll
    for (int t = 0; t < 16; t++) {
        int i = tid + t * 256;
        int r = i >> 5, c4 = i & 31;
        *(float4*)&V1[r * V1_STR + c4 * 4] = F4[i];
    }
    // ---- load partner Gram hi/lo ----
    {
        const uint2* gh = (const uint2*)(g_gram_hi + (size_t)(gj ^ 1) * DDIM * DDIM);
        const uint2* gl = (const uint2*)(g_gram_lo + (size_t)(gj ^ 1) * DDIM * DDIM);
#pragma unroll
        for (int t = 0; t < 16; t++) {
            int i = tid + t * 256;
            int r = i >> 5, s = i & 31;
            *(uint2*)&Bh[r * B_STR + s * 4] = gh[i];
            *(uint2*)&Bl[r * B_STR + s * 4] = gl[i];
        }
    }
    __syncthreads();

    // ================= pass1: V2 = V1 * Gram (nt-pair interleaved) ==========
    {
        float acc[16][4];
#pragma unroll
        for (int n = 0; n < 16; n++)
#pragma unroll
            for (int j = 0; j < 4; j++) acc[n][j] = 0.f;

#pragma unroll 1
        for (int kt = 0; kt < 8; kt++) {
            int k0 = kt * 16 + qid * 2;
            float2 a00 = *(const float2*)&V1[ra * V1_STR + k0];
            float2 a10 = *(const float2*)&V1[(ra + 8) * V1_STR + k0];
            float2 a01 = *(const float2*)&V1[ra * V1_STR + k0 + 8];
            float2 a11 = *(const float2*)&V1[(ra + 8) * V1_STR + k0 + 8];
            uint32_t ah[4], al[4];
            split2(a00.x, a00.y, ah[0], al[0]);
            split2(a10.x, a10.y, ah[1], al[1]);
            split2(a01.x, a01.y, ah[2], al[2]);
            split2(a11.x, a11.y, ah[3], al[3]);
#pragma unroll
            for (int nt = 0; nt < 16; nt += 2) {
                int bnA = nt * 8 + grp, bnB = (nt + 1) * 8 + grp;
                uint32_t bh0a = *(const uint32_t*)&Bh[bnA * B_STR + k0];
                uint32_t bh1a = *(const uint32_t*)&Bh[bnA * B_STR + k0 + 8];
                uint32_t bl0a = *(const uint32_t*)&Bl[bnA * B_STR + k0];
                uint32_t bl1a = *(const uint32_t*)&Bl[bnA * B_STR + k0 + 8];
                uint32_t bh0b = *(const uint32_t*)&Bh[bnB * B_STR + k0];
                uint32_t bh1b = *(const uint32_t*)&Bh[bnB * B_STR + k0 + 8];
                uint32_t bl0b = *(const uint32_t*)&Bl[bnB * B_STR + k0];
                uint32_t bl1b = *(const uint32_t*)&Bl[bnB * B_STR + k0 + 8];
                mma_bf16(acc[nt],     ah, bh0a, bh1a);
                mma_bf16(acc[nt + 1], ah, bh0b, bh1b);
                mma_bf16(acc[nt],     ah, bl0a, bl1a);
                mma_bf16(acc[nt + 1], ah, bl0b, bl1b);
                mma_bf16(acc[nt],     al, bh0a, bh1a);
                mma_bf16(acc[nt + 1], al, bh0b, bh1b);
            }
        }
#pragma unroll
        for (int nt = 0; nt < 16; nt++) {
            int c = nt * 8 + qid * 2;
            *(float2*)&V2[ra * V1_STR + c]       = make_float2(acc[nt][0], acc[nt][1]);
            *(float2*)&V2[(ra + 8) * V1_STR + c] = make_float2(acc[nt][2], acc[nt][3]);
        }
    }
    __syncthreads();

    // ---- swap B to W^2 hi/lo ----
    {
        const uint2* gh = (const uint2*)g_w2_hi;
        const uint2* gl = (const uint2*)g_w2_lo;
#pragma unroll
        for (int t = 0; t < 16; t++) {
            int i = tid + t * 256;
            int r = i >> 5, s = i & 31;
            *(uint2*)&Bh[r * B_STR + s * 4] = gh[i];
            *(uint2*)&Bl[r * B_STR + s * 4] = gl[i];
        }
    }
    __syncthreads();

    // ================= pass2: acc-cycled issue (distance 3) =================
    for (int half = 0; half < 2; half++) {
        float aN[8][4], a1[8][4], a2[8][4];
#pragma unroll
        for (int n = 0; n < 8; n++)
#pragma unroll
            for (int j = 0; j < 4; j++) { aN[n][j] = 0.f; a1[n][j] = 0.f; a2[n][j] = 0.f; }

#pragma unroll 1
        for (int kt = 0; kt < 8; kt++) {
            int k0 = kt * 16 + qid * 2;
            float2 x00 = *(const float2*)&V1[ra * V1_STR + k0];
            float2 x10 = *(const float2*)&V1[(ra + 8) * V1_STR + k0];
            float2 x01 = *(const float2*)&V1[ra * V1_STR + k0 + 8];
            float2 x11 = *(const float2*)&V1[(ra + 8) * V1_STR + k0 + 8];
            float2 y00 = *(const float2*)&V2[ra * V1_STR + k0];
            float2 y10 = *(const float2*)&V2[(ra + 8) * V1_STR + k0];
            float2 y01 = *(const float2*)&V2[ra * V1_STR + k0 + 8];
            float2 y11 = *(const float2*)&V2[(ra + 8) * V1_STR + k0 + 8];

            uint32_t nh[4], nl[4], s1h[4], s1l[4], s2h[4], s2l[4];
            split2(x00.x * y00.x, x00.y * y00.y, nh[0], nl[0]);
            split2(x10.x * y10.x, x10.y * y10.y, nh[1], nl[1]);
            split2(x01.x * y01.x, x01.y * y01.y, nh[2], nl[2]);
            split2(x11.x * y11.x, x11.y * y11.y, nh[3], nl[3]);
            split2(x00.x * x00.x, x00.y * x00.y, s1h[0], s1l[0]);
            split2(x10.x * x10.x, x10.y * x10.y, s1h[1], s1l[1]);
            split2(x01.x * x01.x, x01.y * x01.y, s1h[2], s1l[2]);
            split2(x11.x * x11.x, x11.y * x11.y, s1h[3], s1l[3]);
            split2(y00.x * y00.x, y00.y * y00.y, s2h[0], s2l[0]);
            split2(y10.x * y10.x, y10.y * y10.y, s2h[1], s2l[1]);
            split2(y01.x * y01.x, y01.y * y01.y, s2h[2], s2l[2]);
            split2(y11.x * y11.x, y11.y * y11.y, s2h[3], s2l[3]);

            const __nv_bfloat16* bhp = &Bh[(half * 64 + grp) * B_STR + k0];
            const __nv_bfloat16* blp = &Bl[(half * 64 + grp) * B_STR + k0];
#pragma unroll
            for (int nt = 0; nt < 8; nt++) {
                uint32_t bh0 = *(const uint32_t*)(bhp);
                uint32_t bh1 = *(const uint32_t*)(bhp + 8);
                uint32_t bl0 = *(const uint32_t*)(blp);
                uint32_t bl1 = *(const uint32_t*)(blp + 8);
                bhp += 8 * B_STR; blp += 8 * B_STR;
                // per-acc order unchanged: (h,bh), (h,bl), (l,bh)
                mma_bf16(aN[nt], nh,  bh0, bh1);
                mma_bf16(a1[nt], s1h, bh0, bh1);
                mma_bf16(a2[nt], s2h, bh0, bh1);
                mma_bf16(aN[nt], nh,  bl0, bl1);
                mma_bf16(a1[nt], s1h, bl0, bl1);
                mma_bf16(a2[nt], s2h, bl0, bl1);
                mma_bf16(aN[nt], nl,  bh0, bh1);
                mma_bf16(a1[nt], s1l, bh0, bh1);
                mma_bf16(a2[nt], s2l, bh0, bh1);
            }
        }
        // ---- epilogue ----
        size_t orow0 = (size_t)(row0 + ra) * DDIM;
        size_t orow1 = (size_t)(row0 + ra + 8) * DDIM;
#pragma unroll
        for (int nt = 0; nt < 8; nt++) {
            int col = half * 64 + nt * 8 + qid * 2;
            float d0 = fmaxf(sqrtf(a1[nt][0] * a2[nt][0]), 1e-8f);
            float d1 = fmaxf(sqrtf(a1[nt][1] * a2[nt][1]), 1e-8f);
            float d2 = fmaxf(sqrtf(a1[nt][2] * a2[nt][2]), 1e-8f);
            float d3 = fmaxf(sqrtf(a1[nt][3] * a2[nt][3]), 1e-8f);
            *(float2*)&out[orow0 + col] = make_float2(aN[nt][0] / d0, aN[nt][1] / d1);
            *(float2*)&out[orow1 + col] = make_float2(aN[nt][2] / d2, aN[nt][3] / d3);
        }
    }
}

// ---------------------------------------------------------------------------
extern "C" void kernel_launch(void* const* d_in, const int* in_sizes, int n_in,
                              void* d_out, int out_size) {
    const float* feats = nullptr;
    const float* mp_w  = nullptr;
    for (int i = 0; i < n_in; i++) {
        if (in_sizes[i] == 16777216)     feats = (const float*)d_in[i];
        else if (in_sizes[i] == 16384)   mp_w  = (const float*)d_in[i];
    }
    float* out = (float*)d_out;
    if (!feats || !mp_w || !out) return;

    cudaFuncSetAttribute((const void*)k_main,
                         cudaFuncAttributeMaxDynamicSharedMemorySize, SMEM_MAIN);
    cudaFuncSetAttribute((const void*)k_gram_t,
                         cudaFuncAttributeMaxDynamicSharedMemorySize, SMEM_GRAM);

    k_w2    <<<64, 256>>>(mp_w);
    k_gram_t<<<NGRAPH * GSPLIT, 256, SMEM_GRAM>>>(feats);
    k_gsplit<<<NGRAPH, 256>>>();
    k_main  <<<NGRAPH * (LNODES / 128), 256, SMEM_MAIN>>>(feats, out);
}